// round 12
// baseline (speedup 1.0000x reference)
#include <cuda_runtime.h>
#include <cstdint>
#include <math_constants.h>

#define NI    1024
#define NC    201
#define TT    100
#define ROW   (NC * TT)           // 20100
#define NPAIR (NI * NC)
#define NQ4   (NC * 25)           // 5025 float4 per row
#define TOT4  (NI * NQ4)          // 5,145,600
#define GRID2 1184                // k_sp grid

// -------- scratch (no allocations; zero at module load) --------
__device__ double         g_acc;            // running total (reset by k_sp tail)
__device__ unsigned char  g_wm[NPAIR];      // weight mask bytes (fully rewritten each run)
__device__ unsigned char  g_isbg[NI];
__device__ float          g_bgGat[NI * 3];  // bg gather range sums [rare, common, freq+bg]
__device__ int            g_done1;          // k_lab completion counter (reset by its tail)
__device__ int            g_done2;          // k_sp completion counter (reset by its tail)

// ======================= threefry2x32 (JAX-exact) =======================
__host__ __device__ constexpr uint32_t rotl32(uint32_t x, int r) {
    return (x << r) | (x >> (32 - r));
}
struct TF2 { uint32_t a, b; };

__host__ __device__ constexpr TF2 tf2x32(uint32_t k0, uint32_t k1,
                                         uint32_t x0, uint32_t x1) {
    uint32_t ks2 = k0 ^ k1 ^ 0x1BD11BDAu;
    uint32_t kk[3] = {k0, k1, ks2};
    const int R0[4] = {13, 15, 26, 6};
    const int R1[4] = {17, 29, 16, 24};
    uint32_t v0 = x0 + k0, v1 = x1 + k1;
    for (int i = 0; i < 5; i++) {
        for (int j = 0; j < 4; j++) {
            int r = (i % 2 == 0) ? R0[j] : R1[j];
            v0 += v1; v1 = rotl32(v1, r); v1 ^= v0;
        }
        v0 += kk[(i + 1) % 3];
        v1 += kk[(i + 2) % 3] + (uint32_t)(i + 1);
    }
    return TF2{v0, v1};
}

constexpr TF2      S98 = tf2x32(0u, 42u, 98u, 198u);
constexpr TF2      S99 = tf2x32(0u, 42u, 99u, 199u);
constexpr uint32_t KLA = S98.b, KLB = S99.b;
constexpr TF2      SP0 = tf2x32(KLA, KLB, 0u, 2u);
constexpr TF2      SP1 = tf2x32(KLA, KLB, 1u, 3u);
constexpr uint32_t K1A = SP0.a, K1B = SP1.a;
constexpr uint32_t K2A = SP0.b, K2B = SP1.b;

__device__ __forceinline__ float tf_uniform(uint32_t ka, uint32_t kb, int n) {
    TF2 r = (n < 512) ? tf2x32(ka, kb, (uint32_t)n,         (uint32_t)(n + 512))
                      : tf2x32(ka, kb, (uint32_t)(n - 512), (uint32_t)n);
    uint32_t bits = (n < 512) ? r.a : r.b;
    return __uint_as_float((bits >> 9) | 0x3f800000u) - 1.0f;
}

// ======================= K1: labels stream + wm + gather + tail ============
__global__ __launch_bounds__(256) void k_lab(const float* __restrict__ labels,
                                             const float* __restrict__ cls) {
    __shared__ union {
        struct { float best[8][100]; int bi[8][100]; } pa;   // argmax (6.4 KB)
        struct { int idx[NI]; float u1[NI]; float u2[NI];
                 unsigned char sel[NI]; } tl;                // tail (13.3 KB)
    } u;
    __shared__ int    sLab[TT];
    __shared__ double sGat[NC];
    __shared__ float  sG3[3];
    __shared__ double sRed[8];
    __shared__ int    sLast, sCnt;

    const int n    = blockIdx.x;
    const int tid  = threadIdx.x;
    const int w    = tid >> 5;
    const int lane = tid & 31;

    if (tid < NC) sGat[tid] = 0.0;
    if (tid >= NC && tid < NC + 3) sG3[tid - NC] = 0.f;

    const float* lrow = labels + (size_t)n * ROW;
    const float* crow = cls    + (size_t)n * ROW;

    // ---- per-warp partial argmax over strided class subset (MLP=8) ----
    if (lane < 25) {
        float b0 = -CUDART_INF_F, b1 = -CUDART_INF_F,
              b2 = -CUDART_INF_F, b3 = -CUDART_INF_F;
        int i0 = 0, i1 = 0, i2 = 0, i3 = 0;
        #pragma unroll 8
        for (int c = w; c < NC; c += 8) {
            float4 v = __ldg((const float4*)(lrow + c * TT) + lane);
            if (v.x > b0) { b0 = v.x; i0 = c; }
            if (v.y > b1) { b1 = v.y; i1 = c; }
            if (v.z > b2) { b2 = v.z; i2 = c; }
            if (v.w > b3) { b3 = v.w; i3 = c; }
        }
        int t = lane * 4;
        u.pa.best[w][t + 0] = b0; u.pa.bi[w][t + 0] = i0;
        u.pa.best[w][t + 1] = b1; u.pa.bi[w][t + 1] = i1;
        u.pa.best[w][t + 2] = b2; u.pa.bi[w][t + 2] = i2;
        u.pa.best[w][t + 3] = b3; u.pa.bi[w][t + 3] = i3;
    }
    __syncthreads();

    // ---- combine partials; first-max tie-break (lower c wins) ----
    if (tid < TT) {
        float b = u.pa.best[0][tid]; int bi = u.pa.bi[0][tid];
        #pragma unroll
        for (int ww = 1; ww < 8; ww++) {
            float v = u.pa.best[ww][tid]; int c = u.pa.bi[ww][tid];
            if (v > b || (v == b && c < bi)) { b = v; bi = c; }
        }
        sLab[tid] = bi;
    }
    __syncthreads();

    const int  lab99 = sLab[TT - 1];
    const bool isbg  = (lab99 == NC - 1);
    if (tid == 0) g_isbg[n] = (unsigned char)isbg;

    // ---- gather: sum_t x[n, lab[t], t] binned per class ----
    if (tid < TT) {
        int lb = sLab[tid];
        atomicAdd(&sGat[lb], (double)__ldg(crow + (size_t)lb * TT + tid));
    }
    __syncthreads();

    // ---- per-class: wm (non-bg) + gather dot; bg -> range partials ----
    float neg = 0.f;
    if (tid < NC) {
        float g = (float)sGat[tid];
        if (!isbg) {
            float x99 = __ldg(crow + (size_t)tid * TT + (TT - 1));
            float sg  = 1.f / (1.f + __expf(-x99));
            bool wm = (tid == lab99) || (sg >= 0.3f);
            g_wm[n * NC + tid] = (unsigned char)wm;
            if (wm) neg = g;
        } else if (g != 0.f) {
            int r = (tid >= 150) ? 2 : (tid >= 50 ? 1 : 0);
            atomicAdd(&sG3[r], g);
        }
    }

    // block reduce of gather dot (non-bg)
    #pragma unroll
    for (int o = 16; o; o >>= 1) neg += __shfl_xor_sync(0xffffffffu, neg, o);
    if (lane == 0) sRed[w] = (double)neg;
    __syncthreads();
    if (tid == 0 && !isbg) {
        double s = 0.0;
        #pragma unroll
        for (int i = 0; i < 8; i++) s += sRed[i];
        atomicAdd(&g_acc, -s);
    }
    if (isbg && tid < 3) g_bgGat[n * 3 + tid] = sG3[tid];

    // ================= last-done block: bg selection tail =================
    __syncthreads();                      // u.pa reads complete before union reuse
    if (tid == 0) {
        __threadfence();
        sLast = (atomicAdd(&g_done1, 1) == NI - 1);
    }
    __syncthreads();
    if (!sLast) return;
    __threadfence();

    if (tid == 0) sCnt = 0;
    __syncthreads();

    // compact bg rows + uniforms
    for (int i = tid; i < NI; i += 256) {
        if (__ldcg(&g_isbg[i])) {
            int p = atomicAdd(&sCnt, 1);
            u.tl.idx[p] = i;
            u.tl.u1[p]  = tf_uniform(K1A, K1B, i);
            u.tl.u2[p]  = tf_uniform(K2A, K2B, i);
        }
    }
    __syncthreads();

    const int nbg = sCnt;
    const int kr  = nbg / 100;            // int(n_bg * 0.01)
    const int kc  = nbg / 10;             // int(n_bg * 0.10)

    // stable-argsort ranks among bg rows
    for (int i = tid; i < nbg; i += 256) {
        float u1 = u.tl.u1[i], u2 = u.tl.u2[i];
        int   m  = u.tl.idx[i];
        int r1 = 0, r2 = 0;
        for (int j = 0; j < nbg; j++) {
            float a = u.tl.u1[j], b = u.tl.u2[j];
            int  mj = u.tl.idx[j];
            r1 += (a < u1) || (a == u1 && mj < m);
            r2 += (b < u2) || (b == u2 && mj < m);
        }
        u.tl.sel[i] = (unsigned char)((r1 < kr ? 2u : 0u) | (r2 < kc ? 4u : 0u));
    }
    __syncthreads();

    // bg wm bytes (read by k_sp)
    for (int q = tid; q < nbg * NC; q += 256) {
        int i = q / NC;
        int c = q - i * NC;
        unsigned f = u.tl.sel[i];
        bool wm = (c >= 150) || ((f & 2u) && c < 50) ||
                  ((f & 4u) && c >= 50 && c < 150);
        g_wm[u.tl.idx[i] * NC + c] = (unsigned char)wm;
    }

    // bg gather dot (negative contribution)
    double acc = 0.0;
    for (int i = tid; i < nbg; i += 256) {
        const float* G = &g_bgGat[u.tl.idx[i] * 3];
        unsigned f = u.tl.sel[i];
        acc += (double)__ldcg(&G[2]);
        if (f & 2u) acc += (double)__ldcg(&G[0]);
        if (f & 4u) acc += (double)__ldcg(&G[1]);
    }
    #pragma unroll
    for (int o = 16; o; o >>= 1) acc += __shfl_xor_sync(0xffffffffu, acc, o);
    if (lane == 0) sRed[w] = acc;
    __syncthreads();
    if (tid == 0) {
        double s = 0.0;
        #pragma unroll
        for (int i = 0; i < 8; i++) s += sRed[i];
        atomicAdd(&g_acc, -s);
        g_done1 = 0;                      // reset for next graph replay
    }
}

// ======================= K2: flat masked softplus stream + finalize ========
// log-product trick: sum_i log2(1+e_i) = log2(prod_i (1+e_i)) — 1 log2 per float4.
__global__ __launch_bounds__(256) void k_sp(const float* __restrict__ cls,
                                            float* __restrict__ out) {
    __shared__ double sRed[8];
    __shared__ int    sLast;

    const int tid  = threadIdx.x;
    const int w    = tid >> 5;
    const int lane = tid & 31;
    const int stride = GRID2 * 256;

    float acc = 0.f;
    for (int q = blockIdx.x * 256 + tid; q < TOT4; q += stride) {
        if (g_wm[q / 25]) {                       // skip dead classes (~20%)
            float4 x = __ldg((const float4*)cls + q);
            float m = fmaxf(x.x, 0.f) + fmaxf(x.y, 0.f)
                    + fmaxf(x.z, 0.f) + fmaxf(x.w, 0.f);
            float t0 = 1.f + __expf(-fabsf(x.x));
            float t1 = 1.f + __expf(-fabsf(x.y));
            float t2 = 1.f + __expf(-fabsf(x.z));
            float t3 = 1.f + __expf(-fabsf(x.w));
            float prod = (t0 * t1) * (t2 * t3);   // in [1,16]
            acc += m + 0.69314718056f * __log2f(prod);
        }
    }

    double d = (double)acc;
    #pragma unroll
    for (int o = 16; o; o >>= 1) d += __shfl_xor_sync(0xffffffffu, d, o);
    if (lane == 0) sRed[w] = d;
    __syncthreads();
    if (tid == 0) {
        double s = 0.0;
        #pragma unroll
        for (int i = 0; i < 8; i++) s += sRed[i];
        atomicAdd(&g_acc, s);
        __threadfence();
        sLast = (atomicAdd(&g_done2, 1) == GRID2 - 1);
    }
    __syncthreads();
    if (sLast && tid == 0) {
        double tot = atomicAdd(&g_acc, 0.0);      // all contributions visible
        out[0] = (float)(tot * (1.0 / ((double)NI * (double)TT)));
        g_acc   = 0.0;                            // reset for next graph replay
        g_done2 = 0;
    }
}

// ======================= launcher ==========================================
extern "C" void kernel_launch(void* const* d_in, const int* in_sizes, int n_in,
                              void* d_out, int out_size) {
    const float* cls    = (const float*)d_in[0];   // [1024,201,100]
    const float* labels = (const float*)d_in[1];   // [1024,201,100]
    float* out = (float*)d_out;

    k_lab<<<NI, 256>>>(labels, cls);
    k_sp <<<GRID2, 256>>>(cls, out);
}

// round 13
// speedup vs baseline: 1.4572x; 1.4572x over previous
#include <cuda_runtime.h>
#include <cstdint>
#include <math_constants.h>

#define NI    1024
#define NC    201
#define TT    100
#define ROW   (NC * TT)           // 20100
#define NPAIR (NI * NC)
#define NQ4   (NC * 25)           // 5025 float4 per row
#define TOT4  (NI * NQ4)          // 5,145,600
#define GRID2 1184                // k_sp grid

// -------- scratch (no allocations; zero at module load) --------
__device__ double         g_acc;            // running total (reset by k_sp tail)
__device__ unsigned char  g_wm[NPAIR];      // weight mask bytes (fully rewritten each run)
__device__ unsigned char  g_isbg[NI];
__device__ float          g_bgGat[NI * 3];  // bg gather range sums [rare, common, freq+bg]
__device__ int            g_done1;          // k_lab completion counter (reset by its tail)
__device__ int            g_done2;          // k_sp completion counter (reset by its tail)

// ======================= threefry2x32 (JAX-exact) =======================
__host__ __device__ constexpr uint32_t rotl32(uint32_t x, int r) {
    return (x << r) | (x >> (32 - r));
}
struct TF2 { uint32_t a, b; };

__host__ __device__ constexpr TF2 tf2x32(uint32_t k0, uint32_t k1,
                                         uint32_t x0, uint32_t x1) {
    uint32_t ks2 = k0 ^ k1 ^ 0x1BD11BDAu;
    uint32_t kk[3] = {k0, k1, ks2};
    const int R0[4] = {13, 15, 26, 6};
    const int R1[4] = {17, 29, 16, 24};
    uint32_t v0 = x0 + k0, v1 = x1 + k1;
    for (int i = 0; i < 5; i++) {
        for (int j = 0; j < 4; j++) {
            int r = (i % 2 == 0) ? R0[j] : R1[j];
            v0 += v1; v1 = rotl32(v1, r); v1 ^= v0;
        }
        v0 += kk[(i + 1) % 3];
        v1 += kk[(i + 2) % 3] + (uint32_t)(i + 1);
    }
    return TF2{v0, v1};
}

constexpr TF2      S98 = tf2x32(0u, 42u, 98u, 198u);
constexpr TF2      S99 = tf2x32(0u, 42u, 99u, 199u);
constexpr uint32_t KLA = S98.b, KLB = S99.b;
constexpr TF2      SP0 = tf2x32(KLA, KLB, 0u, 2u);
constexpr TF2      SP1 = tf2x32(KLA, KLB, 1u, 3u);
constexpr uint32_t K1A = SP0.a, K1B = SP1.a;
constexpr uint32_t K2A = SP0.b, K2B = SP1.b;

__device__ __forceinline__ float tf_uniform(uint32_t ka, uint32_t kb, int n) {
    TF2 r = (n < 512) ? tf2x32(ka, kb, (uint32_t)n,         (uint32_t)(n + 512))
                      : tf2x32(ka, kb, (uint32_t)(n - 512), (uint32_t)n);
    uint32_t bits = (n < 512) ? r.a : r.b;
    return __uint_as_float((bits >> 9) | 0x3f800000u) - 1.0f;
}

// ======================= K1: labels stream + wm + gather + tail ============
__global__ __launch_bounds__(256) void k_lab(const float* __restrict__ labels,
                                             const float* __restrict__ cls) {
    __shared__ union {
        struct { float best[8][100]; int bi[8][100]; } pa;   // argmax (6.4 KB)
        struct { int idx[NI]; float u1[NI]; float u2[NI];
                 unsigned char sel[NI]; } tl;                // tail (13.3 KB)
    } u;
    __shared__ int    sLab[TT];
    __shared__ double sGat[NC];
    __shared__ float  sG3[3];
    __shared__ double sRed[8];
    __shared__ int    sLast, sCnt;

    const int n    = blockIdx.x;
    const int tid  = threadIdx.x;
    const int w    = tid >> 5;
    const int lane = tid & 31;

    if (tid < NC) sGat[tid] = 0.0;
    if (tid >= NC && tid < NC + 3) sG3[tid - NC] = 0.f;

    const float* lrow = labels + (size_t)n * ROW;
    const float* crow = cls    + (size_t)n * ROW;

    // ---- per-warp partial argmax over strided class subset ----
    if (lane < 25) {
        float b0 = -CUDART_INF_F, b1 = -CUDART_INF_F,
              b2 = -CUDART_INF_F, b3 = -CUDART_INF_F;
        int i0 = 0, i1 = 0, i2 = 0, i3 = 0;
        #pragma unroll 4
        for (int c = w; c < NC; c += 8) {
            float4 v = __ldg((const float4*)(lrow + c * TT) + lane);
            if (v.x > b0) { b0 = v.x; i0 = c; }
            if (v.y > b1) { b1 = v.y; i1 = c; }
            if (v.z > b2) { b2 = v.z; i2 = c; }
            if (v.w > b3) { b3 = v.w; i3 = c; }
        }
        int t = lane * 4;
        u.pa.best[w][t + 0] = b0; u.pa.bi[w][t + 0] = i0;
        u.pa.best[w][t + 1] = b1; u.pa.bi[w][t + 1] = i1;
        u.pa.best[w][t + 2] = b2; u.pa.bi[w][t + 2] = i2;
        u.pa.best[w][t + 3] = b3; u.pa.bi[w][t + 3] = i3;
    }
    __syncthreads();

    // ---- combine partials; first-max tie-break (lower c wins) ----
    if (tid < TT) {
        float b = u.pa.best[0][tid]; int bi = u.pa.bi[0][tid];
        #pragma unroll
        for (int ww = 1; ww < 8; ww++) {
            float v = u.pa.best[ww][tid]; int c = u.pa.bi[ww][tid];
            if (v > b || (v == b && c < bi)) { b = v; bi = c; }
        }
        sLab[tid] = bi;
    }
    __syncthreads();

    const int  lab99 = sLab[TT - 1];
    const bool isbg  = (lab99 == NC - 1);
    if (tid == 0) g_isbg[n] = (unsigned char)isbg;

    // ---- gather: sum_t x[n, lab[t], t] binned per class ----
    if (tid < TT) {
        int lb = sLab[tid];
        atomicAdd(&sGat[lb], (double)__ldg(crow + (size_t)lb * TT + tid));
    }
    __syncthreads();

    // ---- per-class: wm (non-bg) + gather dot; bg -> range partials ----
    float neg = 0.f;
    if (tid < NC) {
        float g = (float)sGat[tid];
        if (!isbg) {
            float x99 = __ldg(crow + (size_t)tid * TT + (TT - 1));
            float sg  = 1.f / (1.f + __expf(-x99));
            bool wm = (tid == lab99) || (sg >= 0.3f);
            g_wm[n * NC + tid] = (unsigned char)wm;
            if (wm) neg = g;
        } else if (g != 0.f) {
            int r = (tid >= 150) ? 2 : (tid >= 50 ? 1 : 0);
            atomicAdd(&sG3[r], g);
        }
    }

    // block reduce of gather dot (non-bg)
    #pragma unroll
    for (int o = 16; o; o >>= 1) neg += __shfl_xor_sync(0xffffffffu, neg, o);
    if (lane == 0) sRed[w] = (double)neg;
    __syncthreads();
    if (tid == 0 && !isbg) {
        double s = 0.0;
        #pragma unroll
        for (int i = 0; i < 8; i++) s += sRed[i];
        atomicAdd(&g_acc, -s);
    }
    if (isbg && tid < 3) g_bgGat[n * 3 + tid] = sG3[tid];

    // ================= last-done block: bg selection tail =================
    __syncthreads();                      // u.pa reads complete before union reuse
    if (tid == 0) {
        __threadfence();
        sLast = (atomicAdd(&g_done1, 1) == NI - 1);
    }
    __syncthreads();
    if (!sLast) return;
    __threadfence();

    if (tid == 0) sCnt = 0;
    __syncthreads();

    // compact bg rows + uniforms
    for (int i = tid; i < NI; i += 256) {
        if (__ldcg(&g_isbg[i])) {
            int p = atomicAdd(&sCnt, 1);
            u.tl.idx[p] = i;
            u.tl.u1[p]  = tf_uniform(K1A, K1B, i);
            u.tl.u2[p]  = tf_uniform(K2A, K2B, i);
        }
    }
    __syncthreads();

    const int nbg = sCnt;
    const int kr  = nbg / 100;            // int(n_bg * 0.01)
    const int kc  = nbg / 10;             // int(n_bg * 0.10)

    // stable-argsort ranks among bg rows
    for (int i = tid; i < nbg; i += 256) {
        float u1 = u.tl.u1[i], u2 = u.tl.u2[i];
        int   m  = u.tl.idx[i];
        int r1 = 0, r2 = 0;
        for (int j = 0; j < nbg; j++) {
            float a = u.tl.u1[j], b = u.tl.u2[j];
            int  mj = u.tl.idx[j];
            r1 += (a < u1) || (a == u1 && mj < m);
            r2 += (b < u2) || (b == u2 && mj < m);
        }
        u.tl.sel[i] = (unsigned char)((r1 < kr ? 2u : 0u) | (r2 < kc ? 4u : 0u));
    }
    __syncthreads();

    // bg wm bytes (read by k_sp)
    for (int q = tid; q < nbg * NC; q += 256) {
        int i = q / NC;
        int c = q - i * NC;
        unsigned f = u.tl.sel[i];
        bool wm = (c >= 150) || ((f & 2u) && c < 50) ||
                  ((f & 4u) && c >= 50 && c < 150);
        g_wm[u.tl.idx[i] * NC + c] = (unsigned char)wm;
    }

    // bg gather dot (negative contribution)
    double acc = 0.0;
    for (int i = tid; i < nbg; i += 256) {
        const float* G = &g_bgGat[u.tl.idx[i] * 3];
        unsigned f = u.tl.sel[i];
        acc += (double)__ldcg(&G[2]);
        if (f & 2u) acc += (double)__ldcg(&G[0]);
        if (f & 4u) acc += (double)__ldcg(&G[1]);
    }
    #pragma unroll
    for (int o = 16; o; o >>= 1) acc += __shfl_xor_sync(0xffffffffu, acc, o);
    if (lane == 0) sRed[w] = acc;
    __syncthreads();
    if (tid == 0) {
        double s = 0.0;
        #pragma unroll
        for (int i = 0; i < 8; i++) s += sRed[i];
        atomicAdd(&g_acc, -s);
        g_done1 = 0;                      // reset for next graph replay
    }
}

// ======================= K2: flat masked softplus stream + finalize ========
// log-product: sum_i log2(1+e_i) = log2(prod_i (1+e_i)), prod in [1,16] — exact
// in fp32, cuts 4 LG2 -> 1 LG2 per float4 (kernel is MUFU-bound).
__global__ __launch_bounds__(256) void k_sp(const float* __restrict__ cls,
                                            float* __restrict__ out) {
    __shared__ double sRed[8];
    __shared__ int    sLast;

    const int tid  = threadIdx.x;
    const int w    = tid >> 5;
    const int lane = tid & 31;
    const int stride = GRID2 * 256;

    float acc = 0.f;
    #pragma unroll 2
    for (int q = blockIdx.x * 256 + tid; q < TOT4; q += stride) {
        if (g_wm[q / 25]) {                       // skip dead classes (~20%)
            float4 x = __ldg((const float4*)cls + q);
            float m = fmaxf(x.x, 0.f) + fmaxf(x.y, 0.f)
                    + fmaxf(x.z, 0.f) + fmaxf(x.w, 0.f);
            float t0 = 1.f + __expf(-fabsf(x.x));
            float t1 = 1.f + __expf(-fabsf(x.y));
            float t2 = 1.f + __expf(-fabsf(x.z));
            float t3 = 1.f + __expf(-fabsf(x.w));
            float prod = (t0 * t1) * (t2 * t3);   // in [1,16]
            acc += m + 0.69314718056f * __log2f(prod);
        }
    }

    double d = (double)acc;
    #pragma unroll
    for (int o = 16; o; o >>= 1) d += __shfl_xor_sync(0xffffffffu, d, o);
    if (lane == 0) sRed[w] = d;
    __syncthreads();
    if (tid == 0) {
        double s = 0.0;
        #pragma unroll
        for (int i = 0; i < 8; i++) s += sRed[i];
        atomicAdd(&g_acc, s);
        __threadfence();
        sLast = (atomicAdd(&g_done2, 1) == GRID2 - 1);
    }
    __syncthreads();
    if (sLast && tid == 0) {
        double tot = atomicAdd(&g_acc, 0.0);      // all contributions visible
        out[0] = (float)(tot * (1.0 / ((double)NI * (double)TT)));
        g_acc   = 0.0;                            // reset for next graph replay
        g_done2 = 0;
    }
}

// ======================= launcher ==========================================
extern "C" void kernel_launch(void* const* d_in, const int* in_sizes, int n_in,
                              void* d_out, int out_size) {
    const float* cls    = (const float*)d_in[0];   // [1024,201,100]
    const float* labels = (const float*)d_in[1];   // [1024,201,100]
    float* out = (float*)d_out;

    k_lab<<<NI, 256>>>(labels, cls);
    k_sp <<<GRID2, 256>>>(cls, out);
}